// round 10
// baseline (speedup 1.0000x reference)
#include <cuda_runtime.h>
#include <cstdint>

// Problem dims (fixed by the dataset)
#define BATCH 64
#define CIN   512
#define TLEN  1024
#define COUT  256

#define BT 128   // t-tile
#define BO 64    // o-tile
#define BK 16    // k-tile

// Intermediate y (post-GEMM, post-BN) in [B][T][COUT] layout (o contiguous
// so the LIF kernel is perfectly coalesced across o). 64 MiB static scratch.
__device__ float g_y[(size_t)BATCH * TLEN * COUT];

// ---- packed f32x2 helpers (sm_100+ PTX) ------------------------------------
__device__ __forceinline__ unsigned long long pk2(float lo, float hi) {
    unsigned long long r;
    asm("mov.b64 %0, {%1, %2};" : "=l"(r) : "f"(lo), "f"(hi));
    return r;
}
__device__ __forceinline__ void unpk2(unsigned long long v, float& lo, float& hi) {
    asm("mov.b64 {%0, %1}, %2;" : "=f"(lo), "=f"(hi) : "l"(v));
}
#define FFMA2(acc, a, b) \
    asm("fma.rn.f32x2 %0, %1, %2, %0;" : "+l"(acc) : "l"(a), "l"(b))

// ============================================================================
// Kernel 1: fused conv1x1 GEMM + BatchNorm (inference) into g_y[B][T][COUT]
//   y[b,t,o] = (sum_c x[b,c,t] * W[o,c]) * sc[o] + sh[o]
// 128x64 tile per block, 256 threads, 8x4 microtile as 4x4 packed f32x2.
// ============================================================================
__global__ __launch_bounds__(256) void gemm_bn_kernel(
    const float* __restrict__ x,      // [B, CIN, TLEN]
    const float* __restrict__ W,      // [COUT, CIN]
    const float* __restrict__ gamma,  // [COUT]
    const float* __restrict__ beta,   // [COUT]
    const float* __restrict__ rmean,  // [COUT]
    const float* __restrict__ rvar)   // [COUT]
{
    __shared__ __align__(16) float As[BK][BT];
    __shared__ __align__(16) float Bs[BK][BO];

    const int tid   = threadIdx.x;
    const int tBase = blockIdx.x * BT;
    const int oBase = blockIdx.y * BO;
    const int b     = blockIdx.z;

    const int rowg = tid >> 4;   // 0..15 -> t_local = rowg*8
    const int colg = tid & 15;   // 0..15 -> o_local = colg*4

    const float* xb = x + (size_t)b * CIN * TLEN + tBase;

    unsigned long long acc[4][4];
#pragma unroll
    for (int p = 0; p < 4; p++)
#pragma unroll
        for (int j = 0; j < 4; j++) acc[p][j] = 0ull;

    // A-load decode (hoisted): 512 float4 per tile, tid + 256*i
    const int cA0 = (tid) >> 5;            // 0..7
    const int t4A = (tid) & 31;
    // B-load decode: 256 float4 per tile
    const int oB  = tid >> 2;              // 0..63
    const int ccB = (tid & 3) * 4;         // 0,4,8,12

    for (int k0 = 0; k0 < CIN; k0 += BK) {
        // --- load A tile: x[b, k0+c, tBase + 0..127] (t contiguous, coalesced)
#pragma unroll
        for (int i = 0; i < 2; i++) {
            const int c = cA0 + i * 8;
            float4 v = *(const float4*)(xb + (size_t)(k0 + c) * TLEN + t4A * 4);
            *(float4*)&As[c][t4A * 4] = v;
        }
        // --- load B tile: W[oBase+o, k0 + 0..15], transpose into Bs[c][o]
        {
            float4 v = *(const float4*)(W + (size_t)(oBase + oB) * CIN + k0 + ccB);
            Bs[ccB + 0][oB] = v.x;
            Bs[ccB + 1][oB] = v.y;
            Bs[ccB + 2][oB] = v.z;
            Bs[ccB + 3][oB] = v.w;
        }
        __syncthreads();

#pragma unroll
        for (int c = 0; c < BK; c++) {
            float4 A0 = *(const float4*)&As[c][rowg * 8];
            float4 A1 = *(const float4*)&As[c][rowg * 8 + 4];
            float4 Bv = *(const float4*)&Bs[c][colg * 4];

            unsigned long long a2[4], b2[4];
            a2[0] = pk2(A0.x, A0.y);
            a2[1] = pk2(A0.z, A0.w);
            a2[2] = pk2(A1.x, A1.y);
            a2[3] = pk2(A1.z, A1.w);
            b2[0] = pk2(Bv.x, Bv.x);
            b2[1] = pk2(Bv.y, Bv.y);
            b2[2] = pk2(Bv.z, Bv.z);
            b2[3] = pk2(Bv.w, Bv.w);

#pragma unroll
            for (int p = 0; p < 4; p++)
#pragma unroll
                for (int j = 0; j < 4; j++) FFMA2(acc[p][j], a2[p], b2[j]);
        }
        __syncthreads();
    }

    // --- epilogue: BN affine, store to g_y[b][t][o]
    float sc[4], sh[4];
#pragma unroll
    for (int j = 0; j < 4; j++) {
        const int o = oBase + colg * 4 + j;
        float inv = 1.0f / sqrtf(rvar[o] + 1e-5f);
        sc[j] = gamma[o] * inv;
        sh[j] = beta[o] - rmean[o] * sc[j];
    }

    float* op = g_y + ((size_t)b * TLEN + tBase + rowg * 8) * COUT + oBase + colg * 4;
#pragma unroll
    for (int p = 0; p < 4; p++) {
        float l0, h0, l1, h1, l2, h2, l3, h3;
        unpk2(acc[p][0], l0, h0);
        unpk2(acc[p][1], l1, h1);
        unpk2(acc[p][2], l2, h2);
        unpk2(acc[p][3], l3, h3);
        float4 r0 = make_float4(fmaf(l0, sc[0], sh[0]), fmaf(l1, sc[1], sh[1]),
                                fmaf(l2, sc[2], sh[2]), fmaf(l3, sc[3], sh[3]));
        float4 r1 = make_float4(fmaf(h0, sc[0], sh[0]), fmaf(h1, sc[1], sh[1]),
                                fmaf(h2, sc[2], sh[2]), fmaf(h3, sc[3], sh[3]));
        *(float4*)(op + (size_t)(2 * p) * COUT)     = r0;
        *(float4*)(op + (size_t)(2 * p + 1) * COUT) = r1;
    }
}

// ============================================================================
// Kernel 2: LIF recurrence over T + time-mean.
//   v += (y - v)/2 ; spike = (v >= 1) ; v = spike ? 0 : v ; out = mean(spike)
// One thread per (b, o). Reads are o-contiguous -> fully coalesced.
// Loads batched 16-deep ahead of the dependent recurrence chain for MLP.
// ============================================================================
__global__ __launch_bounds__(128) void lif_kernel(float* __restrict__ out)
{
    const int idx = blockIdx.x * 128 + threadIdx.x;   // 0 .. 16383
    const int b = idx >> 8;
    const int o = idx & 255;

    const float* p = g_y + (size_t)b * TLEN * COUT + o;

    float v = 0.0f;
    float sum = 0.0f;

#pragma unroll 1
    for (int t0 = 0; t0 < TLEN; t0 += 16) {
        float yv[16];
#pragma unroll
        for (int j = 0; j < 16; j++) yv[j] = p[(size_t)j * COUT];
        p += (size_t)16 * COUT;
#pragma unroll
        for (int j = 0; j < 16; j++) {
            // exact reference order: v + (y - v)/TAU, TAU=2 (x0.5 is exact)
            float u = v + (yv[j] - v) * 0.5f;
            bool sp = (u >= 1.0f);
            sum += sp ? 1.0f : 0.0f;
            v = sp ? 0.0f : u;
        }
    }
    out[idx] = sum * (1.0f / 1024.0f);   // /1024 exact, sum is exact integer
}

// ============================================================================
extern "C" void kernel_launch(void* const* d_in, const int* in_sizes, int n_in,
                              void* d_out, int out_size)
{
    const float* x     = (const float*)d_in[0];
    const float* W     = (const float*)d_in[1];
    const float* gamma = (const float*)d_in[2];
    const float* beta  = (const float*)d_in[3];
    const float* rmean = (const float*)d_in[4];
    const float* rvar  = (const float*)d_in[5];
    float* out = (float*)d_out;

    dim3 g1(TLEN / BT, COUT / BO, BATCH);   // 8 x 4 x 64 = 2048 blocks
    gemm_bn_kernel<<<g1, 256>>>(x, W, gamma, beta, rmean, rvar);

    lif_kernel<<<(BATCH * COUT) / 128, 128>>>(out);   // 128 blocks x 128 thr
}

// round 11
// speedup vs baseline: 1.0020x; 1.0020x over previous
#include <cuda_runtime.h>
#include <cstdint>

// Problem dims (fixed by the dataset)
#define BATCH 64
#define CIN   512
#define TLEN  1024
#define COUT  256

#define BT 128   // t-tile
#define BO 64    // o-tile
#define BK 16    // k-tile

// Intermediate y (post-GEMM, post-BN) in [B][T][COUT] layout (o contiguous
// so the LIF kernel is perfectly coalesced across o). 64 MiB static scratch.
__device__ float g_y[(size_t)BATCH * TLEN * COUT];

// ---- packed f32x2 helpers (sm_100+ PTX) ------------------------------------
__device__ __forceinline__ unsigned long long pk2(float lo, float hi) {
    unsigned long long r;
    asm("mov.b64 %0, {%1, %2};" : "=l"(r) : "f"(lo), "f"(hi));
    return r;
}
__device__ __forceinline__ void unpk2(unsigned long long v, float& lo, float& hi) {
    asm("mov.b64 {%0, %1}, %2;" : "=f"(lo), "=f"(hi) : "l"(v));
}
#define FFMA2(acc, a, b) \
    asm("fma.rn.f32x2 %0, %1, %2, %0;" : "+l"(acc) : "l"(a), "l"(b))

// ============================================================================
// Kernel 1: fused conv1x1 GEMM + BatchNorm (inference) into g_y[B][T][COUT]
//   y[b,t,o] = (sum_c x[b,c,t] * W[o,c]) * sc[o] + sh[o]
// 128x64 tile per block, 256 threads, 8x4 microtile as 4x4 packed f32x2.
// ============================================================================
__global__ __launch_bounds__(256) void gemm_bn_kernel(
    const float* __restrict__ x,      // [B, CIN, TLEN]
    const float* __restrict__ W,      // [COUT, CIN]
    const float* __restrict__ gamma,  // [COUT]
    const float* __restrict__ beta,   // [COUT]
    const float* __restrict__ rmean,  // [COUT]
    const float* __restrict__ rvar)   // [COUT]
{
    __shared__ __align__(16) float As[BK][BT];
    __shared__ __align__(16) float Bs[BK][BO];

    const int tid   = threadIdx.x;
    const int tBase = blockIdx.x * BT;
    const int oBase = blockIdx.y * BO;
    const int b     = blockIdx.z;

    const int rowg = tid >> 4;   // 0..15 -> t_local = rowg*8
    const int colg = tid & 15;   // 0..15 -> o_local = colg*4

    const float* xb = x + (size_t)b * CIN * TLEN + tBase;

    unsigned long long acc[4][4];
#pragma unroll
    for (int p = 0; p < 4; p++)
#pragma unroll
        for (int j = 0; j < 4; j++) acc[p][j] = 0ull;

    // A-load decode (hoisted): 512 float4 per tile, tid + 256*i
    const int cA0 = (tid) >> 5;            // 0..7
    const int t4A = (tid) & 31;
    // B-load decode: 256 float4 per tile
    const int oB  = tid >> 2;              // 0..63
    const int ccB = (tid & 3) * 4;         // 0,4,8,12

    for (int k0 = 0; k0 < CIN; k0 += BK) {
        // --- load A tile: x[b, k0+c, tBase + 0..127] (t contiguous, coalesced)
#pragma unroll
        for (int i = 0; i < 2; i++) {
            const int c = cA0 + i * 8;
            float4 v = *(const float4*)(xb + (size_t)(k0 + c) * TLEN + t4A * 4);
            *(float4*)&As[c][t4A * 4] = v;
        }
        // --- load B tile: W[oBase+o, k0 + 0..15], transpose into Bs[c][o]
        {
            float4 v = *(const float4*)(W + (size_t)(oBase + oB) * CIN + k0 + ccB);
            Bs[ccB + 0][oB] = v.x;
            Bs[ccB + 1][oB] = v.y;
            Bs[ccB + 2][oB] = v.z;
            Bs[ccB + 3][oB] = v.w;
        }
        __syncthreads();

#pragma unroll
        for (int c = 0; c < BK; c++) {
            float4 A0 = *(const float4*)&As[c][rowg * 8];
            float4 A1 = *(const float4*)&As[c][rowg * 8 + 4];
            float4 Bv = *(const float4*)&Bs[c][colg * 4];

            unsigned long long a2[4], b2[4];
            a2[0] = pk2(A0.x, A0.y);
            a2[1] = pk2(A0.z, A0.w);
            a2[2] = pk2(A1.x, A1.y);
            a2[3] = pk2(A1.z, A1.w);
            b2[0] = pk2(Bv.x, Bv.x);
            b2[1] = pk2(Bv.y, Bv.y);
            b2[2] = pk2(Bv.z, Bv.z);
            b2[3] = pk2(Bv.w, Bv.w);

#pragma unroll
            for (int p = 0; p < 4; p++)
#pragma unroll
                for (int j = 0; j < 4; j++) FFMA2(acc[p][j], a2[p], b2[j]);
        }
        __syncthreads();
    }

    // --- epilogue: BN affine, store to g_y[b][t][o]
    float sc[4], sh[4];
#pragma unroll
    for (int j = 0; j < 4; j++) {
        const int o = oBase + colg * 4 + j;
        float inv = 1.0f / sqrtf(rvar[o] + 1e-5f);
        sc[j] = gamma[o] * inv;
        sh[j] = beta[o] - rmean[o] * sc[j];
    }

    float* op = g_y + ((size_t)b * TLEN + tBase + rowg * 8) * COUT + oBase + colg * 4;
#pragma unroll
    for (int p = 0; p < 4; p++) {
        float l0, h0, l1, h1, l2, h2, l3, h3;
        unpk2(acc[p][0], l0, h0);
        unpk2(acc[p][1], l1, h1);
        unpk2(acc[p][2], l2, h2);
        unpk2(acc[p][3], l3, h3);
        float4 r0 = make_float4(fmaf(l0, sc[0], sh[0]), fmaf(l1, sc[1], sh[1]),
                                fmaf(l2, sc[2], sh[2]), fmaf(l3, sc[3], sh[3]));
        float4 r1 = make_float4(fmaf(h0, sc[0], sh[0]), fmaf(h1, sc[1], sh[1]),
                                fmaf(h2, sc[2], sh[2]), fmaf(h3, sc[3], sh[3]));
        *(float4*)(op + (size_t)(2 * p) * COUT)     = r0;
        *(float4*)(op + (size_t)(2 * p + 1) * COUT) = r1;
    }
}

// ============================================================================
// Kernel 2: LIF recurrence over T + time-mean.
//   v += (y - v)/2 ; spike = (v >= 1) ; v = spike ? 0 : v ; out = mean(spike)
// One thread per (b, o). Reads are o-contiguous -> fully coalesced.
// Loads batched 16-deep ahead of the dependent recurrence chain for MLP.
// ============================================================================
__global__ __launch_bounds__(128) void lif_kernel(float* __restrict__ out)
{
    const int idx = blockIdx.x * 128 + threadIdx.x;   // 0 .. 16383
    const int b = idx >> 8;
    const int o = idx & 255;

    const float* p = g_y + (size_t)b * TLEN * COUT + o;

    float v = 0.0f;
    float sum = 0.0f;

#pragma unroll 1
    for (int t0 = 0; t0 < TLEN; t0 += 16) {
        float yv[16];
#pragma unroll
        for (int j = 0; j < 16; j++) yv[j] = p[(size_t)j * COUT];
        p += (size_t)16 * COUT;
#pragma unroll
        for (int j = 0; j < 16; j++) {
            // exact reference order: v + (y - v)/TAU, TAU=2 (x0.5 is exact)
            float u = v + (yv[j] - v) * 0.5f;
            bool sp = (u >= 1.0f);
            sum += sp ? 1.0f : 0.0f;
            v = sp ? 0.0f : u;
        }
    }
    out[idx] = sum * (1.0f / 1024.0f);   // /1024 exact, sum is exact integer
}

// ============================================================================
extern "C" void kernel_launch(void* const* d_in, const int* in_sizes, int n_in,
                              void* d_out, int out_size)
{
    const float* x     = (const float*)d_in[0];
    const float* W     = (const float*)d_in[1];
    const float* gamma = (const float*)d_in[2];
    const float* beta  = (const float*)d_in[3];
    const float* rmean = (const float*)d_in[4];
    const float* rvar  = (const float*)d_in[5];
    float* out = (float*)d_out;

    dim3 g1(TLEN / BT, COUT / BO, BATCH);   // 8 x 4 x 64 = 2048 blocks
    gemm_bn_kernel<<<g1, 256>>>(x, W, gamma, beta, rmean, rvar);

    lif_kernel<<<(BATCH * COUT) / 128, 128>>>(out);   // 128 blocks x 128 thr
}

// round 14
// speedup vs baseline: 1.1017x; 1.0996x over previous
#include <cuda_runtime.h>
#include <cuda_bf16.h>
#include <cstdint>

// Problem dims (fixed)
#define BATCH 64
#define CIN   512
#define TLEN  1024
#define COUT  256

// GEMM tiling
#define KC      32                 // channels per k-chunk
#define NCHUNK  (CIN/KC)           // 16
#define ROWB    80                 // smem row pitch bytes (32 bf16 = 64B + 16B pad)
#define TILEB   (128*ROWB)         // 10240 B per part tile (128 rows)
#define ABASE   0                  // A parts at dsm+0 (3 tiles)
#define BBASE   (3*TILEB)          // B parts at dsm+30720 (3 tiles)
#define DSMB    (6*TILEB)          // 61440 B dynamic smem

// 64 MiB intermediate y in [B][T][COUT] (o contiguous -> coalesced LIF reads)
__device__ float g_y[(size_t)BATCH * TLEN * COUT];
// Pre-split, pre-tiled W parts: [(ot*16+kc)*3+p] tiles, each the exact smem image
__device__ __align__(16) unsigned char g_Wt[2 * NCHUNK * 3 * TILEB];

// ---------------------------------------------------------------------------
// 3-way bf16 split: x ~= h + m + l (residuals exact in fp32)
__device__ __forceinline__ void split3(float x, __nv_bfloat16& h,
                                       __nv_bfloat16& m, __nv_bfloat16& l) {
    h = __float2bfloat16(x);
    float r = x - __bfloat162float(h);
    m = __float2bfloat16(r);
    l = __float2bfloat16(r - __bfloat162float(m));
}
__device__ __forceinline__ uint32_t pack2(__nv_bfloat16 a, __nv_bfloat16 b) {
    __nv_bfloat162 v; v.x = a; v.y = b;
    return *reinterpret_cast<uint32_t*>(&v);
}
// m16n8k16 row.col bf16 -> f32 accumulate (sm_80 feature; legal on compute_103)
__device__ __forceinline__ void mma16816(float* d, const uint32_t* a,
                                         const uint32_t* b) {
    asm volatile(
        "mma.sync.aligned.m16n8k16.row.col.f32.bf16.bf16.f32 "
        "{%0,%1,%2,%3}, {%4,%5,%6,%7}, {%8,%9}, {%0,%1,%2,%3};\n"
        : "+f"(d[0]), "+f"(d[1]), "+f"(d[2]), "+f"(d[3])
        : "r"(a[0]), "r"(a[1]), "r"(a[2]), "r"(a[3]), "r"(b[0]), "r"(b[1]));
}

// ============================================================================
// Kernel 0: split W into 3 bf16 part tiles laid out as exact smem images.
// One thread per (tile, o-row, c4-group of 4 channels).  98304 threads.
// ============================================================================
__global__ __launch_bounds__(256) void wprep_kernel(const float* __restrict__ W)
{
    int g  = blockIdx.x * 256 + threadIdx.x;   // 0..98303
    int c4 = g & 7;
    int o  = (g >> 3) & 127;
    int ti = g >> 10;                          // 0..95 = (ot*16+kc)*3+p
    int p  = ti % 3;
    int q  = ti / 3;
    int kc = q & 15;
    int ot = q >> 4;

    float4 wv = *(const float4*)(W + (size_t)(ot * 128 + o) * CIN + kc * KC + c4 * 4);

    float vv[4] = {wv.x, wv.y, wv.z, wv.w};
    __nv_bfloat16 part[4];
#pragma unroll
    for (int j = 0; j < 4; j++) {
        __nv_bfloat16 h, m, l;
        split3(vv[j], h, m, l);
        part[j] = (p == 0) ? h : (p == 1) ? m : l;
    }
    *reinterpret_cast<uint2*>(g_Wt + (size_t)ti * TILEB + o * ROWB + c4 * 8) =
        make_uint2(pack2(part[0], part[1]), pack2(part[2], part[3]));
}

// ============================================================================
// Kernel 1: split-bf16 HMMA GEMM + BN -> g_y[b][t][o]
//   D[o][t] = sum_{(p,q): p+q<=2} sum_c Wp[o][c] * xq[c][t]
// grid (8 t-tiles, 2 o-tiles, 64 b), 256 thr, warps 2(o)x4(t), 64x32/warp.
// ============================================================================
__global__ __launch_bounds__(256, 2) void gemm_mma_kernel(
    const float* __restrict__ x,
    const float* __restrict__ gamma, const float* __restrict__ beta,
    const float* __restrict__ rmean, const float* __restrict__ rvar)
{
    extern __shared__ __align__(16) char dsm[];

    const int tid    = threadIdx.x;
    const int wid    = tid >> 5;
    const int lane   = tid & 31;
    const int grp    = lane >> 2;     // 0..7
    const int t4     = lane & 3;      // 0..3
    const int warp_o = wid >> 2;      // 0..1
    const int warp_t = wid & 3;       // 0..3

    const int tBase = blockIdx.x * 128;
    const int ot    = blockIdx.y;
    const int oBase = ot * 128;
    const int b     = blockIdx.z;

    const float* xb = x + (size_t)b * CIN * TLEN + tBase;

    float acc[4][4][4];
#pragma unroll
    for (int mi = 0; mi < 4; mi++)
#pragma unroll
        for (int ni = 0; ni < 4; ni++)
#pragma unroll
            for (int r = 0; r < 4; r++) acc[mi][ni][r] = 0.0f;

    // per-thread fragment byte offsets (conflict-free by the pitch-80 trick)
    const int aoff = (warp_o * 64 + grp) * ROWB + t4 * 4;
    const int boff = (warp_t * 32 + grp) * ROWB + t4 * 4;

    for (int kc = 0; kc < NCHUNK; kc++) {
        __syncthreads();   // smem free from previous chunk's mma reads

        // ---- A: copy pre-built part tiles (30720 B, L2-resident) -----------
        {
            const uint4* src = (const uint4*)(g_Wt + (size_t)((ot * NCHUNK + kc) * 3) * TILEB);
            uint4* dst = (uint4*)dsm;
            for (int i = tid; i < 3 * TILEB / 16; i += 256) dst[i] = src[i];
        }
        // ---- B: load x chunk, 3-way split, transpose to [t][k] rows --------
#pragma unroll
        for (int i = 0; i < 4; i++) {
            int pos = tid + 256 * i;          // 0..1023
            int t  = pos & 127;
            int c4 = pos >> 7;                // 0..7
            const float* xp = xb + (size_t)(kc * KC + c4 * 4) * TLEN + t;
            float v0 = xp[0 * TLEN], v1 = xp[1 * TLEN];
            float v2 = xp[2 * TLEN], v3 = xp[3 * TLEN];
            __nv_bfloat16 h[4], m[4], l[4];
            split3(v0, h[0], m[0], l[0]);
            split3(v1, h[1], m[1], l[1]);
            split3(v2, h[2], m[2], l[2]);
            split3(v3, h[3], m[3], l[3]);
            char* bp = dsm + BBASE + t * ROWB + c4 * 8;
            *(uint2*)(bp)             = make_uint2(pack2(h[0], h[1]), pack2(h[2], h[3]));
            *(uint2*)(bp + TILEB)     = make_uint2(pack2(m[0], m[1]), pack2(m[2], m[3]));
            *(uint2*)(bp + 2 * TILEB) = make_uint2(pack2(l[0], l[1]), pack2(l[2], l[3]));
        }
        __syncthreads();

        // ---- 6 part-pairs x 2 k16-steps of HMMA ----------------------------
        const int PP[6] = {0, 0, 1, 0, 1, 2};
        const int QQ[6] = {0, 1, 0, 2, 1, 0};
#pragma unroll
        for (int pi = 0; pi < 6; pi++) {
            const char* Ap = dsm + PP[pi] * TILEB + aoff;
            const char* Bp = dsm + BBASE + QQ[pi] * TILEB + boff;
#pragma unroll
            for (int ks = 0; ks < 2; ks++) {
                uint32_t afr[4][4], bfr[4][2];
#pragma unroll
                for (int mi = 0; mi < 4; mi++) {
                    const char* ab = Ap + mi * (16 * ROWB) + ks * 32;
                    afr[mi][0] = *(const uint32_t*)(ab);
                    afr[mi][1] = *(const uint32_t*)(ab + 8 * ROWB);
                    afr[mi][2] = *(const uint32_t*)(ab + 16);
                    afr[mi][3] = *(const uint32_t*)(ab + 8 * ROWB + 16);
                }
#pragma unroll
                for (int ni = 0; ni < 4; ni++) {
                    const char* bb = Bp + ni * (8 * ROWB) + ks * 32;
                    bfr[ni][0] = *(const uint32_t*)(bb);
                    bfr[ni][1] = *(const uint32_t*)(bb + 16);
                }
#pragma unroll
                for (int mi = 0; mi < 4; mi++)
#pragma unroll
                    for (int ni = 0; ni < 4; ni++)
                        mma16816(acc[mi][ni], afr[mi], bfr[ni]);
            }
        }
    }

    // ---- epilogue: BN + transpose via smem, coalesced float4 stores --------
    float* se = (float*)dsm;   // [t 128][o 68 pitch] fp32, 34816 B
#pragma unroll
    for (int h = 0; h < 2; h++) {
        __syncthreads();
        if (warp_o == h) {
#pragma unroll
            for (int mi = 0; mi < 4; mi++) {
                // BN coeffs for this thread's two o-rows of tile mi
                float sc0, sh0, sc1, sh1;
                {
                    int o0 = oBase + h * 64 + mi * 16 + grp;
                    int o1 = o0 + 8;
                    sc0 = gamma[o0] * rsqrtf(rvar[o0] + 1e-5f);
                    sh0 = beta[o0] - rmean[o0] * sc0;
                    sc1 = gamma[o1] * rsqrtf(rvar[o1] + 1e-5f);
                    sh1 = beta[o1] - rmean[o1] * sc1;
                }
#pragma unroll
                for (int ni = 0; ni < 4; ni++) {
                    int tc = warp_t * 32 + ni * 8 + 2 * t4;
                    int oc = mi * 16 + grp;
                    se[(tc    ) * 68 + oc    ] = fmaf(acc[mi][ni][0], sc0, sh0);
                    se[(tc + 1) * 68 + oc    ] = fmaf(acc[mi][ni][1], sc0, sh0);
                    se[(tc    ) * 68 + oc + 8] = fmaf(acc[mi][ni][2], sc1, sh1);
                    se[(tc + 1) * 68 + oc + 8] = fmaf(acc[mi][ni][3], sc1, sh1);
                }
            }
        }
        __syncthreads();
        // cooperative coalesced store of the 128t x 64o half
#pragma unroll
        for (int i = 0; i < 8; i++) {
            int idx = tid + 256 * i;        // 0..2047
            int o4  = idx & 15;
            int t   = idx >> 4;
            float4 v = *(const float4*)(se + t * 68 + o4 * 4);
            *(float4*)(g_y + ((size_t)(b * TLEN + tBase + t)) * COUT
                       + oBase + h * 64 + o4 * 4) = v;
        }
    }
}

// ============================================================================
// Kernel 2: LIF recurrence + time-mean, 4-deep chunk pipeline (48 loads live).
// ============================================================================
__global__ __launch_bounds__(128) void lif_kernel(float* __restrict__ out)
{
    const int idx = blockIdx.x * 128 + threadIdx.x;   // 0..16383
    const int b = idx >> 8;
    const int o = idx & 255;
    const float* p = g_y + (size_t)b * TLEN * COUT + o;

    float B0[16], B1[16], B2[16], B3[16];
    float v = 0.0f, sum = 0.0f;

#define LOADC(BUF, c) do {                                                    \
    const float* _q = p + (size_t)(c) * 16 * COUT;                            \
    _Pragma("unroll")                                                         \
    for (int j = 0; j < 16; j++) BUF[j] = _q[(size_t)j * COUT];               \
} while (0)
#define PROC(BUF) do {                                                        \
    _Pragma("unroll")                                                         \
    for (int j = 0; j < 16; j++) {                                            \
        float u = v + (BUF[j] - v) * 0.5f;   /* exact: (y-v)/TAU, TAU=2 */    \
        bool sp = (u >= 1.0f);                                                \
        sum += sp ? 1.0f : 0.0f;                                              \
        v = sp ? 0.0f : u;                                                    \
    }                                                                         \
} while (0)

    LOADC(B0, 0); LOADC(B1, 1); LOADC(B2, 2);
#pragma unroll 1
    for (int i = 0; i < 60; i += 4) {
        LOADC(B3, i + 3); PROC(B0);
        LOADC(B0, i + 4); PROC(B1);
        LOADC(B1, i + 5); PROC(B2);
        LOADC(B2, i + 6); PROC(B3);
    }
    LOADC(B3, 63);
    PROC(B0); PROC(B1); PROC(B2); PROC(B3);

    out[idx] = sum * (1.0f / 1024.0f);
#undef LOADC
#undef PROC
}

// ============================================================================
extern "C" void kernel_launch(void* const* d_in, const int* in_sizes, int n_in,
                              void* d_out, int out_size)
{
    const float* x     = (const float*)d_in[0];
    const float* W     = (const float*)d_in[1];
    const float* gamma = (const float*)d_in[2];
    const float* beta  = (const float*)d_in[3];
    const float* rmean = (const float*)d_in[4];
    const float* rvar  = (const float*)d_in[5];
    float* out = (float*)d_out;

    cudaFuncSetAttribute(gemm_mma_kernel,
                         cudaFuncAttributeMaxDynamicSharedMemorySize, DSMB);

    wprep_kernel<<<384, 256>>>(W);

    dim3 g1(TLEN / 128, COUT / 128, BATCH);   // 8 x 2 x 64 = 1024 blocks
    gemm_mma_kernel<<<g1, 256, DSMB>>>(x, gamma, beta, rmean, rvar);

    lif_kernel<<<(BATCH * COUT) / 128, 128>>>(out);
}